// round 1
// baseline (speedup 1.0000x reference)
#include <cuda_runtime.h>
#include <cuda_bf16.h>
#include <math.h>

// CBOW negative-sampling loss.
// Inputs (metadata order):
//   d_in[0] i_emb        float32 [200001, 50]
//   d_in[1] o_emb        float32 [200001, 50]
//   d_in[2] target_wids  int32   [B]
//   d_in[3] context_wids int32   [B, 10]
//   d_in[4] neg_wids     int32   [B, 10]
// Output: scalar float32 = -(sum log_sigmoid(pos) + sum log_sigmoid(-neg))

#define DIM   50
#define CTX   10
#define NNEG  10
#define WPB   8          // warps (batch elements) per block
#define MAX_BLOCKS 4096

__device__ float g_partials[MAX_BLOCKS];

__device__ __forceinline__ float log_sigmoid(float x) {
    // stable: min(x,0) - log1p(exp(-|x|))
    return fminf(x, 0.0f) - log1pf(__expf(-fabsf(x)));
}

__global__ void __launch_bounds__(WPB * 32)
cbow_loss_kernel(const float* __restrict__ i_emb,
                 const float* __restrict__ o_emb,
                 const int*   __restrict__ tgt_w,
                 const int*   __restrict__ ctx_w,
                 const int*   __restrict__ neg_w,
                 int B)
{
    const int warp = threadIdx.x >> 5;
    const int lane = threadIdx.x & 31;
    const int b    = blockIdx.x * WPB + warp;

    float warp_loss = 0.0f;

    if (b < B) {
        // Per-warp index fetch: lanes 0..9 hold the ctx / neg ids, broadcast later.
        int my_ctx = (lane < CTX)  ? ctx_w[b * CTX  + lane] : 0;
        int my_neg = (lane < NNEG) ? neg_w[b * NNEG + lane] : 0;
        const int t = tgt_w[b];                 // uniform load (L1 broadcast)

        const int d0   = lane;                  // < 32 < DIM always valid
        const int d1   = lane + 32;
        const bool has1 = (d1 < DIM);           // lanes 0..17

        // Sum of context embeddings (mean folded into score scale below).
        float a0 = 0.0f, a1 = 0.0f;
        #pragma unroll
        for (int j = 0; j < CTX; ++j) {
            const int c = __shfl_sync(0xffffffffu, my_ctx, j);
            const float* __restrict__ row = i_emb + (size_t)c * DIM;
            a0 += row[d0];
            if (has1) a1 += row[d1];
        }

        // Positive score partial.
        const float* __restrict__ trow = o_emb + (size_t)t * DIM;
        float t0 = trow[d0];
        float t1 = has1 ? trow[d1] : 0.0f;
        float pos = a0 * t0 + a1 * t1;

        // Negative score partials.
        float negp[NNEG];
        #pragma unroll
        for (int n = 0; n < NNEG; ++n) {
            const int q = __shfl_sync(0xffffffffu, my_neg, n);
            const float* __restrict__ nrow = o_emb + (size_t)q * DIM;
            float n0 = nrow[d0];
            float n1 = has1 ? nrow[d1] : 0.0f;
            negp[n] = a0 * n0 + a1 * n1;
        }

        // Butterfly reduce all 11 dot products across the warp.
        #pragma unroll
        for (int off = 16; off > 0; off >>= 1) {
            pos += __shfl_xor_sync(0xffffffffu, pos, off);
            #pragma unroll
            for (int n = 0; n < NNEG; ++n)
                negp[n] += __shfl_xor_sync(0xffffffffu, negp[n], off);
        }

        // mean over CTX folded in here.
        const float inv_ctx = 1.0f / (float)CTX;
        float loss = log_sigmoid(pos * inv_ctx);
        #pragma unroll
        for (int n = 0; n < NNEG; ++n)
            loss += log_sigmoid(-negp[n] * inv_ctx);
        warp_loss = loss;   // identical on all lanes
    }

    // Block reduce: one value per warp.
    __shared__ float s_warp[WPB];
    if (lane == 0) s_warp[warp] = warp_loss;
    __syncthreads();
    if (threadIdx.x == 0) {
        float s = 0.0f;
        #pragma unroll
        for (int w = 0; w < WPB; ++w) s += s_warp[w];
        g_partials[blockIdx.x] = s;
    }
}

__global__ void reduce_kernel(float* __restrict__ out, int nblk)
{
    __shared__ float s[256];
    float acc = 0.0f;
    for (int i = threadIdx.x; i < nblk; i += 256)
        acc += g_partials[i];
    s[threadIdx.x] = acc;
    __syncthreads();
    #pragma unroll
    for (int stride = 128; stride > 0; stride >>= 1) {
        if (threadIdx.x < stride) s[threadIdx.x] += s[threadIdx.x + stride];
        __syncthreads();
    }
    if (threadIdx.x == 0) out[0] = -s[0];
}

extern "C" void kernel_launch(void* const* d_in, const int* in_sizes, int n_in,
                              void* d_out, int out_size)
{
    const float* i_emb = (const float*)d_in[0];
    const float* o_emb = (const float*)d_in[1];
    const int*   tgt   = (const int*)d_in[2];
    const int*   ctx   = (const int*)d_in[3];
    const int*   neg   = (const int*)d_in[4];
    float*       out   = (float*)d_out;

    const int B = in_sizes[2];
    const int nblk = (B + WPB - 1) / WPB;   // 2048 for B=16384

    cbow_loss_kernel<<<nblk, WPB * 32>>>(i_emb, o_emb, tgt, ctx, neg, B);
    reduce_kernel<<<1, 256>>>(out, nblk);
}

// round 2
// speedup vs baseline: 1.0094x; 1.0094x over previous
#include <cuda_runtime.h>
#include <cuda_bf16.h>
#include <math.h>

// CBOW negative-sampling loss, fused single-kernel version.
// Inputs (metadata order):
//   d_in[0] i_emb        float32 [200001, 50]
//   d_in[1] o_emb        float32 [200001, 50]
//   d_in[2] target_wids  int32   [B]
//   d_in[3] context_wids int32   [B, 10]
//   d_in[4] neg_wids     int32   [B, 10]
// Output: scalar float32 = -(sum log_sigmoid(pos) + sum log_sigmoid(-neg))
//
// Layout: one warp per batch element. Rows are 50 fp32 = 200 B, 8-byte
// aligned, so lanes 0..24 each load one float2 covering the whole row in a
// single LDG.64. Final reduction fused via threadfence-reduction (last block
// reduces per-block partials in deterministic order, writes -(sum), resets
// the counter for graph replay).

#define DIM   50
#define CTX   10
#define NNEG  10
#define WPB   8            // warps (batch elements) per block
#define TPB   (WPB * 32)
#define MAX_BLOCKS 4096

__device__ float g_partials[MAX_BLOCKS];
__device__ unsigned int g_count = 0;

__device__ __forceinline__ float log_sigmoid(float x) {
    // stable: min(x,0) - log1p(exp(-|x|))
    return fminf(x, 0.0f) - log1pf(__expf(-fabsf(x)));
}

__global__ void __launch_bounds__(TPB)
cbow_loss_kernel(const float* __restrict__ i_emb,
                 const float* __restrict__ o_emb,
                 const int*   __restrict__ tgt_w,
                 const int*   __restrict__ ctx_w,
                 const int*   __restrict__ neg_w,
                 float*       __restrict__ out,
                 int B, int nblk)
{
    const int warp = threadIdx.x >> 5;
    const int lane = threadIdx.x & 31;
    const int b    = blockIdx.x * WPB + warp;

    float warp_loss = 0.0f;

    if (b < B) {
        // lanes 0..9 fetch the ctx / neg ids; broadcast via shfl later.
        int my_ctx = (lane < CTX)  ? ctx_w[b * CTX  + lane] : 0;
        int my_neg = (lane < NNEG) ? neg_w[b * NNEG + lane] : 0;
        const int t = tgt_w[b];

        const bool act = (lane < DIM / 2);       // lanes 0..24 carry data

        // Sum of context embeddings (mean folded into score scale below).
        float a0 = 0.0f, a1 = 0.0f;
        #pragma unroll
        for (int j = 0; j < CTX; ++j) {
            const int c = __shfl_sync(0xffffffffu, my_ctx, j);
            if (act) {
                const float2 v = __ldg((const float2*)(i_emb + (size_t)c * DIM) + lane);
                a0 += v.x;
                a1 += v.y;
            }
        }

        // Positive score partial.
        float pos = 0.0f;
        if (act) {
            const float2 tv = __ldg((const float2*)(o_emb + (size_t)t * DIM) + lane);
            pos = a0 * tv.x + a1 * tv.y;
        }

        // Negative score partials.
        float negp[NNEG];
        #pragma unroll
        for (int n = 0; n < NNEG; ++n) {
            const int q = __shfl_sync(0xffffffffu, my_neg, n);
            float p = 0.0f;
            if (act) {
                const float2 nv = __ldg((const float2*)(o_emb + (size_t)q * DIM) + lane);
                p = a0 * nv.x + a1 * nv.y;
            }
            negp[n] = p;
        }

        // Butterfly reduce all 11 dot products across the warp.
        #pragma unroll
        for (int off = 16; off > 0; off >>= 1) {
            pos += __shfl_xor_sync(0xffffffffu, pos, off);
            #pragma unroll
            for (int n = 0; n < NNEG; ++n)
                negp[n] += __shfl_xor_sync(0xffffffffu, negp[n], off);
        }

        // mean over CTX folded in here.
        const float inv_ctx = 1.0f / (float)CTX;
        float loss = log_sigmoid(pos * inv_ctx);
        #pragma unroll
        for (int n = 0; n < NNEG; ++n)
            loss += log_sigmoid(-negp[n] * inv_ctx);
        warp_loss = loss;   // identical on all lanes
    }

    // Block reduce: one value per warp.
    __shared__ float s_warp[WPB];
    if (lane == 0) s_warp[warp] = warp_loss;
    __syncthreads();

    __shared__ bool s_last;
    if (threadIdx.x == 0) {
        float s = 0.0f;
        #pragma unroll
        for (int w = 0; w < WPB; ++w) s += s_warp[w];
        g_partials[blockIdx.x] = s;
        __threadfence();
        unsigned int prev = atomicAdd(&g_count, 1u);
        s_last = (prev == (unsigned int)(nblk - 1));
    }
    __syncthreads();

    // Last block to finish reduces all per-block partials (fixed order →
    // deterministic result) and writes the final loss.
    if (s_last) {
        __shared__ float s_red[TPB];
        float acc = 0.0f;
        for (int i = threadIdx.x; i < nblk; i += TPB)
            acc += g_partials[i];
        s_red[threadIdx.x] = acc;
        __syncthreads();
        #pragma unroll
        for (int stride = TPB / 2; stride > 0; stride >>= 1) {
            if (threadIdx.x < stride) s_red[threadIdx.x] += s_red[threadIdx.x + stride];
            __syncthreads();
        }
        if (threadIdx.x == 0) {
            out[0] = -s_red[0];
            g_count = 0;          // reset for next graph replay
        }
    }
}

extern "C" void kernel_launch(void* const* d_in, const int* in_sizes, int n_in,
                              void* d_out, int out_size)
{
    const float* i_emb = (const float*)d_in[0];
    const float* o_emb = (const float*)d_in[1];
    const int*   tgt   = (const int*)d_in[2];
    const int*   ctx   = (const int*)d_in[3];
    const int*   neg   = (const int*)d_in[4];
    float*       out   = (float*)d_out;

    const int B = in_sizes[2];
    const int nblk = (B + WPB - 1) / WPB;   // 2048 for B=16384

    cbow_loss_kernel<<<nblk, TPB>>>(i_emb, o_emb, tgt, ctx, neg, out, B, nblk);
}

// round 5
// speedup vs baseline: 1.1233x; 1.1128x over previous
#include <cuda_runtime.h>
#include <cuda_bf16.h>
#include <math.h>

// CBOW negative-sampling loss, fused single-kernel version.
// Inputs (metadata order):
//   d_in[0] i_emb        float32 [200001, 50]
//   d_in[1] o_emb        float32 [200001, 50]
//   d_in[2] target_wids  int32   [B]
//   d_in[3] context_wids int32   [B, 10]
//   d_in[4] neg_wids     int32   [B, 10]
// Output: scalar float32 = -(sum log_sigmoid(pos) + sum log_sigmoid(-neg))
//
// One warp per batch element; lanes 0..24 each hold one float2 of a row.
// Indices are loaded warp-uniform (int2-vectorized). After the butterfly
// reduction the 11 dot products are distributed one-per-lane so log_sigmoid
// is issued ONCE per warp instead of 11 times.

#define DIM   50
#define CTX   10
#define NNEG  10
#define WPB   16           // warps (batch elements) per block
#define TPB   (WPB * 32)
#define MAX_BLOCKS 4096

__device__ float g_partials[MAX_BLOCKS];
__device__ unsigned int g_count = 0;

__global__ void __launch_bounds__(TPB)
cbow_loss_kernel(const float* __restrict__ i_emb,
                 const float* __restrict__ o_emb,
                 const int*   __restrict__ tgt_w,
                 const int*   __restrict__ ctx_w,
                 const int*   __restrict__ neg_w,
                 float*       __restrict__ out,
                 int B, int nblk)
{
    const int warp = threadIdx.x >> 5;
    const int lane = threadIdx.x & 31;
    const int b    = blockIdx.x * WPB + warp;

    float warp_loss = 0.0f;

    if (b < B) {
        // Warp-uniform index loads, int2-vectorized (row base 40B -> 8B aligned).
        const int2* __restrict__ cp = (const int2*)(ctx_w + (size_t)b * CTX);
        const int2* __restrict__ np = (const int2*)(neg_w + (size_t)b * NNEG);
        int cidx[CTX], nidx[NNEG];
        #pragma unroll
        for (int j = 0; j < CTX / 2; ++j) {
            int2 c = __ldg(cp + j);
            cidx[2 * j] = c.x; cidx[2 * j + 1] = c.y;
            int2 q = __ldg(np + j);
            nidx[2 * j] = q.x; nidx[2 * j + 1] = q.y;
        }
        const int t = __ldg(tgt_w + b);

        const bool act = (lane < DIM / 2);       // lanes 0..24 carry row data

        // Sum of context embeddings (mean folded into score scale below).
        float a0 = 0.0f, a1 = 0.0f;
        #pragma unroll
        for (int j = 0; j < CTX; ++j) {
            if (act) {
                const float2 v = __ldg((const float2*)(i_emb + (size_t)cidx[j] * DIM) + lane);
                a0 += v.x;
                a1 += v.y;
            }
        }

        // Positive score partial.
        float pos = 0.0f;
        if (act) {
            const float2 tv = __ldg((const float2*)(o_emb + (size_t)t * DIM) + lane);
            pos = a0 * tv.x + a1 * tv.y;
        }

        // Negative score partials.
        float negp[NNEG];
        #pragma unroll
        for (int n = 0; n < NNEG; ++n) {
            float p = 0.0f;
            if (act) {
                const float2 nv = __ldg((const float2*)(o_emb + (size_t)nidx[n] * DIM) + lane);
                p = a0 * nv.x + a1 * nv.y;
            }
            negp[n] = p;
        }

        // Butterfly reduce all 11 dot products across the warp.
        #pragma unroll
        for (int off = 16; off > 0; off >>= 1) {
            pos += __shfl_xor_sync(0xffffffffu, pos, off);
            #pragma unroll
            for (int n = 0; n < NNEG; ++n)
                negp[n] += __shfl_xor_sync(0xffffffffu, negp[n], off);
        }

        // Distribute: lane 0 -> pos, lane n+1 -> negp[n]; lanes 11..31 dummy.
        float x = pos;
        #pragma unroll
        for (int n = 0; n < NNEG; ++n)
            x = (lane == n + 1) ? negp[n] : x;

        // arg = +pos/CTX on lane 0, -neg/CTX on lanes 1..10 (mean folded in).
        const float inv_ctx = 1.0f / (float)CTX;
        const float scale = (lane == 0) ? inv_ctx : -inv_ctx;
        const float arg   = x * scale;

        // log_sigmoid issued ONCE per warp: min(a,0) - log(1 + exp(-|a|)).
        // __logf arg is in [1,2]; MUFU accuracy ~1e-6 rel, well within 1e-3.
        float ls = fminf(arg, 0.0f) - __logf(1.0f + __expf(-fabsf(arg)));
        ls = (lane <= NNEG) ? ls : 0.0f;         // zero dummy lanes

        // Warp-sum the per-lane losses.
        #pragma unroll
        for (int off = 16; off > 0; off >>= 1)
            ls += __shfl_xor_sync(0xffffffffu, ls, off);
        warp_loss = ls;                          // identical on all lanes
    }

    // Block reduce: one value per warp.
    __shared__ float s_warp[WPB];
    if (lane == 0) s_warp[warp] = warp_loss;
    __syncthreads();

    __shared__ bool s_last;
    if (threadIdx.x == 0) {
        float s = 0.0f;
        #pragma unroll
        for (int w = 0; w < WPB; ++w) s += s_warp[w];
        g_partials[blockIdx.x] = s;
        __threadfence();
        unsigned int prev = atomicAdd(&g_count, 1u);
        s_last = (prev == (unsigned int)(nblk - 1));
    }
    __syncthreads();

    // Last block reduces all per-block partials (fixed order -> deterministic)
    // and writes the final loss; resets the counter for graph replay.
    if (s_last) {
        if (threadIdx.x < 32) {
            float acc = 0.0f;
            for (int i = threadIdx.x; i < nblk; i += 32)
                acc += g_partials[i];
            #pragma unroll
            for (int off = 16; off > 0; off >>= 1)
                acc += __shfl_xor_sync(0xffffffffu, acc, off);
            if (threadIdx.x == 0) {
                out[0] = -acc;
                g_count = 0;          // reset for next graph replay
            }
        }
    }
}

extern "C" void kernel_launch(void* const* d_in, const int* in_sizes, int n_in,
                              void* d_out, int out_size)
{
    const float* i_emb = (const float*)d_in[0];
    const float* o_emb = (const float*)d_in[1];
    const int*   tgt   = (const int*)d_in[2];
    const int*   ctx   = (const int*)d_in[3];
    const int*   neg   = (const int*)d_in[4];
    float*       out   = (float*)d_out;

    const int B = in_sizes[2];
    const int nblk = (B + WPB - 1) / WPB;   // 1024 for B=16384

    cbow_loss_kernel<<<nblk, TPB>>>(i_emb, o_emb, tgt, ctx, neg, out, B, nblk);
}